// round 13
// baseline (speedup 1.0000x reference)
#include <cuda_runtime.h>
#include <cstdint>

#define NN 16384
#define HH 2048
#define H4 (HH / 4)            // 512 float4 per row
#define KN 25
#define CHUNK 128
#define C4 (CHUNK / 4)         // 32
#define NCHUNK (HH / CHUNK)    // 16
#define RPW 4
#define NWARPS 8
#define NTHREADS 256
#define RPB (NWARPS * RPW)     // 32 rows per block
#define NROWBLK (NN / RPB)     // 512
#define NQ 5
#define NC 5
#define SMEM_BYTES (NC * HH * 4)   // 40960

// HT = this slice also computes the target dots (as a post-pass)
template <bool HT>
__device__ __forceinline__ void run_slice(
    const float* __restrict__ input, const float* __restrict__ weight,
    const float* __restrict__ bias, const int* __restrict__ target,
    const float* __restrict__ sw, const float* __restrict__ s_nb,
    float* __restrict__ out, int rb, int wid, int lane, int kbase)
{
    const int row0 = rb + wid * RPW;

    // single base pointer; r*H4 offsets fold into LDG immediates (rows contiguous)
    const float4* xp = reinterpret_cast<const float4*>(input)
                       + (size_t)row0 * H4 + lane;

    float acc[RPW][NC];
    #pragma unroll
    for (int r = 0; r < RPW; r++)
        #pragma unroll
        for (int j = 0; j < NC; j++) acc[r][j] = 0.f;

    // chunk-0 x prefetch
    float4 x4[RPW];
    #pragma unroll
    for (int r = 0; r < RPW; r++) x4[r] = xp[r * H4];

    const float4* wrow = reinterpret_cast<const float4*>(sw) + lane;

    #pragma unroll 2
    for (int c = 0; c < NCHUNK; c++) {
        // prefetch next chunk's x (consumed next iteration) — load-bearing!
        const int dn = (c + 1 < NCHUNK) ? C4 : 0;
        float4 x4n[RPW];
        #pragma unroll
        for (int r = 0; r < RPW; r++) x4n[r] = xp[r * H4 + dn];

        #pragma unroll
        for (int j = 0; j < NC; j++) {
            float4 w = wrow[j * H4];
            #pragma unroll
            for (int r = 0; r < RPW; r++) {
                float a = acc[r][j];
                a = fmaf(x4[r].x, w.x, a);
                a = fmaf(x4[r].y, w.y, a);
                a = fmaf(x4[r].z, w.z, a);
                a = fmaf(x4[r].w, w.w, a);
                acc[r][j] = a;
            }
        }

        #pragma unroll
        for (int r = 0; r < RPW; r++) x4[r] = x4n[r];
        xp += C4;
        wrow += C4;
    }

    // warp butterfly reduction over lanes (disjoint H slices)
    #pragma unroll
    for (int off = 16; off > 0; off >>= 1) {
        #pragma unroll
        for (int r = 0; r < RPW; r++)
            #pragma unroll
            for (int j = 0; j < NC; j++)
                acc[r][j] += __shfl_xor_sync(0xffffffffu, acc[r][j], off);
    }

    // pmn outputs
    #pragma unroll
    for (int r = 0; r < RPW; r++) {
        const int n = row0 + r;
        float* pmn_row = out + (size_t)2 * NN + (size_t)n * KN + kbase;
        #pragma unroll
        for (int j = 0; j < NC; j++) {
            if (lane == j) pmn_row[j] = __expf(acc[r][j] + s_nb[j]);
        }
    }

    // ---- target-dot post-pass (slice 4 only). x rows are L1/L2-hot from the
    // main loop; registers here reuse the freed accumulator space. ----
    if (HT) {
        int tgt[RPW];
        #pragma unroll
        for (int r = 0; r < RPW; r++) tgt[r] = target[row0 + r];

        const float4* xp2 = reinterpret_cast<const float4*>(input)
                            + (size_t)row0 * H4 + lane;
        const float4* wtp[RPW];
        #pragma unroll
        for (int r = 0; r < RPW; r++)
            wtp[r] = reinterpret_cast<const float4*>(weight)
                     + (size_t)tgt[r] * H4 + lane;

        float acct[RPW];
        #pragma unroll
        for (int r = 0; r < RPW; r++) acct[r] = 0.f;

        #pragma unroll 2
        for (int c = 0; c < NCHUNK; c++) {
            #pragma unroll
            for (int r = 0; r < RPW; r++) {
                float4 xv = xp2[r * H4];
                float4 wv = wtp[r][0];
                float a = acct[r];
                a = fmaf(xv.x, wv.x, a);
                a = fmaf(xv.y, wv.y, a);
                a = fmaf(xv.z, wv.z, a);
                a = fmaf(xv.w, wv.w, a);
                acct[r] = a;
            }
            xp2 += C4;
            #pragma unroll
            for (int r = 0; r < RPW; r++) wtp[r] += C4;
        }

        #pragma unroll
        for (int off = 16; off > 0; off >>= 1)
            #pragma unroll
            for (int r = 0; r < RPW; r++)
                acct[r] += __shfl_xor_sync(0xffffffffu, acct[r], off);

        #pragma unroll
        for (int r = 0; r < RPW; r++) {
            if (lane == r) {   // lanes 0-3 store rows 0-3
                int n = row0 + r;
                out[n] = __expf(acct[r] + bias[tgt[r]]);
            }
        }
    }
}

__global__ __launch_bounds__(NTHREADS, 4)
void nce_kernel(const float* __restrict__ input,
                const float* __restrict__ weight,
                const float* __restrict__ bias,
                const float* __restrict__ unig,
                const int* __restrict__ target,
                const int* __restrict__ noise,
                float* __restrict__ out)
{
    extern __shared__ __align__(16) float sw[];   // 5 x 2048 noise rows
    __shared__ float s_nb[NC];
    __shared__ float s_nu[KN];
    __shared__ int   s_nk[NC];

    const int tid   = threadIdx.x;
    const int lane  = tid & 31;
    const int wid   = tid >> 5;
    const int bid   = blockIdx.x;
    const int rbidx = bid / NQ;
    const int q     = bid - rbidx * NQ;
    const int rb    = rbidx * RPB;
    const int kbase = q * NC;

    if (tid < NC) {
        int nk = noise[kbase + tid];
        s_nk[tid] = nk;
        s_nb[tid] = bias[nk];
    }
    if (q == 0 && tid < KN) s_nu[tid] = unig[noise[tid]];
    __syncthreads();

    // ---- early independent outputs (slice 0 only): pnn + pnt ----
    if (q == 0) {
        const size_t pnn_base = (size_t)2 * NN + (size_t)NN * KN + (size_t)rb * KN;
        #pragma unroll 1
        for (int i = tid; i < RPB * KN; i += NTHREADS)
            out[pnn_base + i] = s_nu[i % KN];
        if (tid < RPB) {
            int n = rb + tid;
            out[NN + n] = unig[target[n]];
        }
    }

    // ---- fill this slice's noise tile into smem (coalesced, once) ----
    {
        const float4* w4 = reinterpret_cast<const float4*>(weight);
        float4* s4 = reinterpret_cast<float4*>(sw);
        #pragma unroll 1
        for (int idx = tid; idx < NC * H4; idx += NTHREADS) {
            int j = idx >> 9;          // / H4
            int h = idx & (H4 - 1);
            s4[idx] = w4[(size_t)s_nk[j] * H4 + h];
        }
    }
    __syncthreads();
    // ======== free-running from here ========

    if (q == 4)
        run_slice<true >(input, weight, bias, target, sw, s_nb, out, rb, wid, lane, 20);
    else if (q == 0)
        run_slice<false>(input, weight, bias, target, sw, s_nb, out, rb, wid, lane, 0);
    else if (q == 1)
        run_slice<false>(input, weight, bias, target, sw, s_nb, out, rb, wid, lane, 5);
    else if (q == 2)
        run_slice<false>(input, weight, bias, target, sw, s_nb, out, rb, wid, lane, 10);
    else
        run_slice<false>(input, weight, bias, target, sw, s_nb, out, rb, wid, lane, 15);
}

extern "C" void kernel_launch(void* const* d_in, const int* in_sizes, int n_in,
                              void* d_out, int out_size) {
    const float* input  = (const float*)d_in[0];
    const float* weight = (const float*)d_in[1];
    const float* bias   = (const float*)d_in[2];
    const float* unig   = (const float*)d_in[3];
    const int*   target = (const int*)d_in[4];
    const int*   noise  = (const int*)d_in[5];
    float* out = (float*)d_out;

    cudaFuncSetAttribute(nce_kernel,
                         cudaFuncAttributeMaxDynamicSharedMemorySize, SMEM_BYTES);
    nce_kernel<<<NROWBLK * NQ, NTHREADS, SMEM_BYTES>>>(input, weight, bias, unig,
                                                       target, noise, out);
}